// round 15
// baseline (speedup 1.0000x reference)
#include <cuda_runtime.h>
#include <cuda_fp16.h>
#include <cstdint>

// Problem constants
#define B_ 8
#define T_ 1024
#define S_ 1024
#define C_ 1024
#define H_ 16
#define D_ 64

#define NX   ((size_t)B_ * T_ * C_)        // 8M
#define NKV  ((size_t)B_ * S_ * 2 * C_)    // 16M

// fp16 scratch (device globals — no allocation allowed)
__device__ __half g_xh[NX];
__device__ __half g_fh[NX];
__device__ __half g_Wch[(size_t)C_ * C_];
__device__ __half g_Wfh[(size_t)2 * C_ * C_];
__device__ __half g_Wph[(size_t)C_ * C_];
__device__ __half g_qh[NX];
__device__ __half g_kvh[NKV];
__device__ __half g_ah[NX];

__device__ __forceinline__ uint32_t smem_to_u32(const void* p) {
    uint32_t a;
    asm("{ .reg .u64 t; cvta.to.shared.u64 t, %1; cvt.u32.u64 %0, t; }"
        : "=r"(a) : "l"(p));
    return a;
}

#define LDSM_X4(r0, r1, r2, r3, addr) \
    asm volatile("ldmatrix.sync.aligned.m8n8.x4.shared.b16 {%0,%1,%2,%3}, [%4];" \
                 : "=r"(r0), "=r"(r1), "=r"(r2), "=r"(r3) : "r"(addr))

#define LDSM_X4_T(r0, r1, r2, r3, addr) \
    asm volatile("ldmatrix.sync.aligned.m8n8.x4.trans.shared.b16 {%0,%1,%2,%3}, [%4];" \
                 : "=r"(r0), "=r"(r1), "=r"(r2), "=r"(r3) : "r"(addr))

#define MMA_FP16(d, a, b) \
    asm volatile("mma.sync.aligned.m16n8k16.row.col.f32.f16.f16.f32 " \
                 "{%0,%1,%2,%3}, {%4,%5,%6,%7}, {%8,%9}, {%0,%1,%2,%3};" \
                 : "+f"((d)[0]), "+f"((d)[1]), "+f"((d)[2]), "+f"((d)[3]) \
                 : "r"((a)[0]), "r"((a)[1]), "r"((a)[2]), "r"((a)[3]), \
                   "r"((b)[0]), "r"((b)[1]))

#define CP_ASYNC16(dst, src) \
    asm volatile("cp.async.cg.shared.global [%0], [%1], 16;" :: "r"(dst), "l"(src))
#define CP_COMMIT() asm volatile("cp.async.commit_group;")
#define CP_WAIT1()  asm volatile("cp.async.wait_group 1;" ::: "memory")

__device__ __forceinline__ uint32_t pack2h(float a, float b) {
    __half2 t = __floats2half2_rn(a, b);
    return *(uint32_t*)&t;
}

// ===========================================================================
// Fused convert kernel: all 5 tensors in one launch (fp32 * mul -> fp16)
// ===========================================================================
#define CVT_N_X   2097152u
#define CVT_N_W1  262144u
#define CVT_N_W2  524288u
#define CVT_B0    (CVT_N_X)
#define CVT_B1    (2u * CVT_N_X)
#define CVT_B2    (CVT_B1 + CVT_N_W1)
#define CVT_B3    (CVT_B2 + CVT_N_W2)
#define CVT_TOTAL (CVT_B3 + CVT_N_W1)            // 5242880 float4s
#define CVT_BLOCKS (CVT_TOTAL / 256u)            // 20480

__global__ __launch_bounds__(256) void cvt_all_kernel(
    const float* __restrict__ x, const float* __restrict__ f,
    const float* __restrict__ Wc, const float* __restrict__ Wf,
    const float* __restrict__ Wp,
    __half* __restrict__ xh, __half* __restrict__ fh,
    __half* __restrict__ Wch, __half* __restrict__ Wfh,
    __half* __restrict__ Wph)
{
    uint32_t i = blockIdx.x * 256u + threadIdx.x;   // float4 index
    const float* src; __half* dst; float mul = 1.f; uint32_t off;
    if (i < CVT_B0)      { src = x;  dst = xh;  off = i; }
    else if (i < CVT_B1) { src = f;  dst = fh;  off = i - CVT_B0; }
    else if (i < CVT_B2) { src = Wc; dst = Wch; off = i - CVT_B1; mul = 0.125f; }
    else if (i < CVT_B3) { src = Wf; dst = Wfh; off = i - CVT_B2; }
    else                 { src = Wp; dst = Wph; off = i - CVT_B3; }
    float4 v = *(const float4*)(src + (size_t)off * 4);
    __half2 h0 = __floats2half2_rn(v.x * mul, v.y * mul);
    __half2 h1 = __floats2half2_rn(v.z * mul, v.w * mul);
    *(__half2*)(dst + (size_t)off * 4)     = h0;
    *(__half2*)(dst + (size_t)off * 4 + 2) = h1;
}

// ===========================================================================
// fp16 mma.sync GEMM core: C[m,n] = sum_k A[m,k]*B[n,k] + bias[n]*biasmul
// CTA tile 128x128, 4 warps (2x2), warp tile 64x64, BK=64,
// 3-stage cp.async pipeline, 2 CTAs/SM, fragment double-buffering.
// ===========================================================================
#define RS2 72
#define TILE2_E (128 * RS2)                  // 9216 el / tile
#define STAGE2_E (2 * TILE2_E)               // A + B
#define NSTAGE 3
#define GEMM_SMEM_BYTES (NSTAGE * STAGE2_E * 2)   // 110592 B
#define GEMM_THREADS 128

__device__ __forceinline__ void gemm_load_stage(
    uint32_t sbase, int stage, const __half* __restrict__ srcA,
    const __half* __restrict__ srcB, int K, int k0, int tid)
{
    const uint32_t so = sbase + (uint32_t)(stage * STAGE2_E) * 2;
#pragma unroll
    for (int it = 0; it < 8; it++) {
        int idx = tid + it * GEMM_THREADS;
        int row = idx >> 3;
        int col = (idx & 7) * 8;
        CP_ASYNC16(so + (uint32_t)(row * RS2 + col) * 2,
                   srcA + (size_t)row * K + k0 + col);
    }
#pragma unroll
    for (int it = 0; it < 8; it++) {
        int idx = tid + it * GEMM_THREADS;
        int row = idx >> 3;
        int col = (idx & 7) * 8;
        CP_ASYNC16(so + (uint32_t)(TILE2_E + row * RS2 + col) * 2,
                   srcB + (size_t)row * K + k0 + col);
    }
}

// A-fragment group load: 4 m-frags for one ks
#define LD_AF(dst, sA, ksv) do { \
    const int kcol_ = (ksv) * 16 + a_col_l; \
    _Pragma("unroll") \
    for (int mi_ = 0; mi_ < 4; mi_++) { \
        uint32_t eo_ = (uint32_t)((wm + mi_ * 16 + a_row_l) * RS2 + kcol_) * 2; \
        LDSM_X4((dst)[mi_][0], (dst)[mi_][1], (dst)[mi_][2], (dst)[mi_][3], \
                (sA) + eo_); \
    } \
} while (0)

// B-fragment group load: one g (2 n-frags)
#define LD_BF(dst, sB, ksv, gv) do { \
    uint32_t eo_ = (uint32_t)((wn + (gv) * 16 + b_row_add + b_r8) * RS2 + \
                              (ksv) * 16 + b_col_add) * 2; \
    LDSM_X4((dst)[0], (dst)[1], (dst)[2], (dst)[3], (sB) + eo_); \
} while (0)

__device__ __forceinline__ void gemm_core(
    uint32_t sbase,
    const __half* __restrict__ srcA,   // A block base (bm applied)
    const __half* __restrict__ srcB,   // B block base (bn applied)
    const float* __restrict__ bias, float biasmul,
    float* __restrict__ Cf, __half* __restrict__ Ch,
    int N, int K, int bm, int bn)
{
    const int tid = threadIdx.x;
    const int lane = tid & 31;
    const int wid = tid >> 5;          // 0..3
    const int wm = (wid & 1) * 64;     // 0,64
    const int wn = (wid >> 1) * 64;    // 0,64

    float acc[4][8][4];
#pragma unroll
    for (int mi = 0; mi < 4; mi++)
#pragma unroll
        for (int nj = 0; nj < 8; nj++)
#pragma unroll
            for (int e = 0; e < 4; e++) acc[mi][nj][e] = 0.f;

    const int a_row_l = lane & 15;
    const int a_col_l = (lane >> 4) * 8;
    const int b_seg = lane >> 3;
    const int b_r8 = lane & 7;
    const int b_row_add = (b_seg >> 1) * 8;
    const int b_col_add = (b_seg & 1) * 8;

    const int nchunk = K >> 6;   // BK=64

    gemm_load_stage(sbase, 0, srcA, srcB, K, 0, tid);
    CP_COMMIT();
    gemm_load_stage(sbase, 1, srcA, srcB, K, 64, tid);
    CP_COMMIT();

    int stage = 0;
    for (int ck = 0; ck < nchunk; ck++) {
        CP_WAIT1();          // stage ck resident (≤1 group pending)
        __syncthreads();

        if (ck + 2 < nchunk) {
            int st2 = stage + 2; if (st2 >= NSTAGE) st2 -= NSTAGE;
            gemm_load_stage(sbase, st2, srcA, srcB, K, (ck + 2) << 6, tid);
        }
        CP_COMMIT();

        const uint32_t st = sbase + (uint32_t)(stage * STAGE2_E) * 2;
        const uint32_t sA = st;
        const uint32_t sB = st + (uint32_t)TILE2_E * 2;

        // ---- fragment-pipelined compute over 4 ks x 4 g ----
        uint32_t af[2][4][4];   // A double buffer (per ks)
        uint32_t bf[2][4];      // B double buffer (per g)
        LD_AF(af[0], sA, 0);
        LD_BF(bf[0], sB, 0, 0);

#pragma unroll
        for (int ks = 0; ks < 4; ks++) {
            const int ab = ks & 1;
#pragma unroll
            for (int g = 0; g < 4; g++) {
                const int bb = (ks * 4 + g) & 1;
                // prefetch next fragments while current MMAs issue
                if (g == 2 && ks < 3) LD_AF(af[ab ^ 1], sA, ks + 1);
                if (g < 3)            LD_BF(bf[bb ^ 1], sB, ks, g + 1);
                else if (ks < 3)      LD_BF(bf[bb ^ 1], sB, ks + 1, 0);
#pragma unroll
                for (int half = 0; half < 2; half++) {
                    int nj = g * 2 + half;
                    uint32_t* bp = bf[bb] + half * 2;
#pragma unroll
                    for (int mi = 0; mi < 4; mi++)
                        MMA_FP16(acc[mi][nj], af[ab][mi], bp);
                }
            }
        }
        stage++; if (stage >= NSTAGE) stage -= NSTAGE;
    }

    const int er = lane >> 2;
    const int ec = (lane & 3) * 2;
#pragma unroll
    for (int mi = 0; mi < 4; mi++) {
#pragma unroll
        for (int nj = 0; nj < 8; nj++) {
            int m0 = bm + wm + mi * 16 + er;
            int n0 = bn + wn + nj * 8 + ec;
            float b0 = __ldg(bias + n0) * biasmul;
            float b1 = __ldg(bias + n0 + 1) * biasmul;
            float v00 = acc[mi][nj][0] + b0, v01 = acc[mi][nj][1] + b1;
            float v10 = acc[mi][nj][2] + b0, v11 = acc[mi][nj][3] + b1;
            if (Cf) {
                *(float2*)(Cf + (size_t)m0 * N + n0) = make_float2(v00, v01);
                *(float2*)(Cf + (size_t)(m0 + 8) * N + n0) = make_float2(v10, v11);
            } else {
                *(__half2*)(Ch + (size_t)m0 * N + n0) = __floats2half2_rn(v00, v01);
                *(__half2*)(Ch + (size_t)(m0 + 8) * N + n0) = __floats2half2_rn(v10, v11);
            }
        }
    }
}

// merged q + kv projection: blockIdx.x < 8 -> q tile, else kv tile
__global__ __launch_bounds__(GEMM_THREADS, 2) void gemm_qkv_kernel(
    const __half* __restrict__ xh, const __half* __restrict__ fh,
    const __half* __restrict__ Wch, const __half* __restrict__ Wfh,
    const float* __restrict__ bc, const float* __restrict__ bf,
    __half* __restrict__ qh, __half* __restrict__ kvh)
{
    extern __shared__ __half sm[];
    const uint32_t sbase = smem_to_u32(sm);
    const int bm = blockIdx.y * 128;
    if (blockIdx.x < 8) {
        const int bn = blockIdx.x * 128;
        gemm_core(sbase, xh + (size_t)bm * C_, Wch + (size_t)bn * C_,
                  bc, 0.125f, nullptr, qh, C_, C_, bm, bn);
    } else {
        const int bn = (blockIdx.x - 8) * 128;
        gemm_core(sbase, fh + (size_t)bm * C_, Wfh + (size_t)bn * C_,
                  bf, 1.f, nullptr, kvh, 2 * C_, C_, bm, bn);
    }
}

// out-projection: fp32 output
__global__ __launch_bounds__(GEMM_THREADS, 2) void gemm_out_kernel(
    const __half* __restrict__ ah, const __half* __restrict__ Wph,
    const float* __restrict__ bp, float* __restrict__ out)
{
    extern __shared__ __half sm[];
    const uint32_t sbase = smem_to_u32(sm);
    const int bm = blockIdx.y * 128;
    const int bn = blockIdx.x * 128;
    gemm_core(sbase, ah + (size_t)bm * C_, Wph + (size_t)bn * C_,
              bp, 1.f, out, nullptr, C_, C_, bm, bn);
}

// ===========================================================================
// fp16 tensor-core flash attention, causal, d=64, Q pre-scaled by 1/sqrt(d).
// Block = 128 q-rows (8 warps x m16), 64-col K/V tiles, 2-stage cp.async.
// (unchanged — known good)
// ===========================================================================
#define FS2 72
#define FKV2_E (64 * FS2)             // 4608 el per array
#define FSTAGE2_E (2 * FKV2_E)        // K, V
#define FLASH_SMEM_BYTES (2 * FSTAGE2_E * 2)   // 36864 B

__device__ __forceinline__ void flash_ldkv(
    uint32_t sb, uint32_t stoff_bytes, const __half* __restrict__ kvh,
    size_t kvrow, int tid)
{
#pragma unroll
    for (int a = 0; a < 2; a++) {            // 0 = K, 1 = V
        const size_t add = a ? (size_t)C_ : 0;
#pragma unroll
        for (int hf = 0; hf < 2; hf++) {
            int c = tid + hf * 256;          // 0..511
            int row = c >> 3;
            int col = (c & 7) * 8;
            const __half* src = kvh + kvrow + (size_t)row * (2 * C_) + add + col;
            uint32_t dst = sb + stoff_bytes +
                (uint32_t)(a * FKV2_E + row * FS2 + col) * 2;
            CP_ASYNC16(dst, src);
        }
    }
}

__global__ __launch_bounds__(256) void flash_fp16_kernel(
    const __half* __restrict__ qh, const __half* __restrict__ kvh,
    __half* __restrict__ oh)
{
    extern __shared__ __half fsm[];
    const uint32_t sb = smem_to_u32(fsm);

    const int qt = blockIdx.x;            // 0..7  (128-row tiles)
    const int h  = blockIdx.y;
    const int b  = blockIdx.z;
    const int tid = threadIdx.x;
    const int lane = tid & 31;
    const int wid = tid >> 5;
    const int wm = wid * 16;

    const int fr = lane >> 2;
    const int fc = (lane & 3) * 2;

    uint32_t qf[4][4];
    {
        const size_t qrow0 = (size_t)(b * T_ + qt * 128 + wm + fr) * C_ + h * D_;
        const size_t qrow8 = qrow0 + (size_t)8 * C_;
#pragma unroll
        for (int ks = 0; ks < 4; ks++) {
            int c0 = ks * 16 + fc;
            qf[ks][0] = *(const uint32_t*)(qh + qrow0 + c0);
            qf[ks][1] = *(const uint32_t*)(qh + qrow8 + c0);
            qf[ks][2] = *(const uint32_t*)(qh + qrow0 + c0 + 8);
            qf[ks][3] = *(const uint32_t*)(qh + qrow8 + c0 + 8);
        }
    }

    float mrow0 = -1e30f, mrow1 = -1e30f, lrow0 = 0.f, lrow1 = 0.f;
    float oacc[8][4];
#pragma unroll
    for (int j = 0; j < 8; j++)
#pragma unroll
        for (int e = 0; e < 4; e++) oacc[j][e] = 0.f;

    const int b_seg = lane >> 3;
    const int b_r8 = lane & 7;
    const int b_row_add = (b_seg >> 1) * 8;
    const int b_col_add = (b_seg & 1) * 8;
    const int v_row_l = lane & 15;
    const int v_col_l = (lane >> 4) * 8;

    const int row_g0 = qt * 128 + wm + fr;
    const int row_g1 = row_g0 + 8;
    const int st_max = 2 * qt + 1;

    flash_ldkv(sb, 0, kvh, (size_t)(b * S_) * (2 * C_) + h * D_, tid);
    CP_COMMIT();

    for (int st = 0; st <= st_max; st++) {
        __syncthreads();
        if (st + 1 <= st_max) {
            flash_ldkv(sb, (uint32_t)(((st + 1) & 1) * FSTAGE2_E) * 2, kvh,
                       (size_t)(b * S_ + (st + 1) * 64) * (2 * C_) + h * D_, tid);
        }
        CP_COMMIT();
        CP_WAIT1();
        __syncthreads();

        const uint32_t stb = sb + (uint32_t)((st & 1) * FSTAGE2_E) * 2;
        const uint32_t sk_b = stb;
        const uint32_t sv_b = stb + (uint32_t)FKV2_E * 2;

        const bool active = (qt * 128 + wm + 15) >= st * 64;
        if (!active) continue;

        float sacc[8][4];
#pragma unroll
        for (int j = 0; j < 8; j++)
#pragma unroll
            for (int e = 0; e < 4; e++) sacc[j][e] = 0.f;

#pragma unroll
        for (int ks = 0; ks < 4; ks++) {
#pragma unroll
            for (int g = 0; g < 4; g++) {
                uint32_t eo = (uint32_t)((g * 16 + b_row_add + b_r8) * FS2 +
                                         ks * 16 + b_col_add) * 2;
                uint32_t bf[4];
                LDSM_X4(bf[0], bf[1], bf[2], bf[3], sk_b + eo);
#pragma unroll
                for (int half = 0; half < 2; half++) {
                    int nj = g * 2 + half;
                    MMA_FP16(sacc[nj], qf[ks], (bf + half * 2));
                }
            }
        }

        if (st >= 2 * qt) {
#pragma unroll
            for (int nj = 0; nj < 8; nj++) {
#pragma unroll
                for (int e = 0; e < 4; e++) {
                    int col = st * 64 + nj * 8 + fc + (e & 1);
                    int row = (e < 2) ? row_g0 : row_g1;
                    if (col > row) sacc[nj][e] = -1e30f;
                }
            }
        }

        float mx0 = -1e30f, mx1 = -1e30f;
#pragma unroll
        for (int nj = 0; nj < 8; nj++) {
            mx0 = fmaxf(mx0, fmaxf(sacc[nj][0], sacc[nj][1]));
            mx1 = fmaxf(mx1, fmaxf(sacc[nj][2], sacc[nj][3]));
        }
        mx0 = fmaxf(mx0, __shfl_xor_sync(0xffffffffu, mx0, 1));
        mx0 = fmaxf(mx0, __shfl_xor_sync(0xffffffffu, mx0, 2));
        mx1 = fmaxf(mx1, __shfl_xor_sync(0xffffffffu, mx1, 1));
        mx1 = fmaxf(mx1, __shfl_xor_sync(0xffffffffu, mx1, 2));

        float mn0 = fmaxf(mrow0, mx0);
        float mn1 = fmaxf(mrow1, mx1);
        float c0 = __expf(mrow0 - mn0);
        float c1 = __expf(mrow1 - mn1);
        mrow0 = mn0; mrow1 = mn1;

        float rs0 = 0.f, rs1 = 0.f;
        uint32_t pf[4][4];
#pragma unroll
        for (int kp = 0; kp < 4; kp++) {
#pragma unroll
            for (int s2 = 0; s2 < 2; s2++) {
                int nj = kp * 2 + s2;
                float p0 = __expf(sacc[nj][0] - mn0);
                float p1 = __expf(sacc[nj][1] - mn0);
                float p2 = __expf(sacc[nj][2] - mn1);
                float p3 = __expf(sacc[nj][3] - mn1);
                rs0 += p0 + p1;
                rs1 += p2 + p3;
                pf[kp][0 + s2 * 2] = pack2h(p0, p1);
                pf[kp][1 + s2 * 2] = pack2h(p2, p3);
            }
        }
        rs0 += __shfl_xor_sync(0xffffffffu, rs0, 1);
        rs0 += __shfl_xor_sync(0xffffffffu, rs0, 2);
        rs1 += __shfl_xor_sync(0xffffffffu, rs1, 1);
        rs1 += __shfl_xor_sync(0xffffffffu, rs1, 2);
        lrow0 = lrow0 * c0 + rs0;
        lrow1 = lrow1 * c1 + rs1;

#pragma unroll
        for (int j = 0; j < 8; j++) {
            oacc[j][0] *= c0; oacc[j][1] *= c0;
            oacc[j][2] *= c1; oacc[j][3] *= c1;
        }

#pragma unroll
        for (int kp = 0; kp < 4; kp++) {
#pragma unroll
            for (int g = 0; g < 4; g++) {
                uint32_t eo = (uint32_t)((kp * 16 + v_row_l) * FS2 +
                                         g * 16 + v_col_l) * 2;
                uint32_t vf[4];
                LDSM_X4_T(vf[0], vf[1], vf[2], vf[3], sv_b + eo);
#pragma unroll
                for (int half = 0; half < 2; half++) {
                    int njd = g * 2 + half;
                    MMA_FP16(oacc[njd], pf[kp], (vf + half * 2));
                }
            }
        }
    }

    const float inv0 = 1.f / lrow0;
    const float inv1 = 1.f / lrow1;
    const size_t orow0 = (size_t)(b * T_ + row_g0) * C_ + h * D_;
    const size_t orow8 = orow0 + (size_t)8 * C_;
#pragma unroll
    for (int njd = 0; njd < 8; njd++) {
        int col = njd * 8 + fc;
        *(__half2*)(oh + orow0 + col) =
            __floats2half2_rn(oacc[njd][0] * inv0, oacc[njd][1] * inv0);
        *(__half2*)(oh + orow8 + col) =
            __floats2half2_rn(oacc[njd][2] * inv1, oacc[njd][3] * inv1);
    }
}

// ---------------------------------------------------------------------------
// Launch
// ---------------------------------------------------------------------------
extern "C" void kernel_launch(void* const* d_in, const int* in_sizes, int n_in,
                              void* d_out, int out_size)
{
    const float* x       = (const float*)d_in[0];
    const float* feature = (const float*)d_in[1];
    const float* Wc      = (const float*)d_in[2];
    const float* bc      = (const float*)d_in[3];
    const float* Wf      = (const float*)d_in[4];
    const float* bf      = (const float*)d_in[5];
    const float* Wp      = (const float*)d_in[6];
    const float* bp      = (const float*)d_in[7];
    float* out           = (float*)d_out;

    __half *xh, *fh, *Wch, *Wfh, *Wph, *qh, *kvh, *ah;
    cudaGetSymbolAddress((void**)&xh, g_xh);
    cudaGetSymbolAddress((void**)&fh, g_fh);
    cudaGetSymbolAddress((void**)&Wch, g_Wch);
    cudaGetSymbolAddress((void**)&Wfh, g_Wfh);
    cudaGetSymbolAddress((void**)&Wph, g_Wph);
    cudaGetSymbolAddress((void**)&qh, g_qh);
    cudaGetSymbolAddress((void**)&kvh, g_kvh);
    cudaGetSymbolAddress((void**)&ah, g_ah);

    cudaFuncSetAttribute(gemm_qkv_kernel,
                         cudaFuncAttributeMaxDynamicSharedMemorySize, GEMM_SMEM_BYTES);
    cudaFuncSetAttribute(gemm_out_kernel,
                         cudaFuncAttributeMaxDynamicSharedMemorySize, GEMM_SMEM_BYTES);
    cudaFuncSetAttribute(flash_fp16_kernel,
                         cudaFuncAttributeMaxDynamicSharedMemorySize, FLASH_SMEM_BYTES);

    // ---- 0) fused convert: all fp32 inputs -> fp16 (Wc pre-scaled) ----
    cvt_all_kernel<<<CVT_BLOCKS, 256>>>(x, feature, Wc, Wf, Wp,
                                        xh, fh, Wch, Wfh, Wph);

    // ---- 1+2) q and kv projections, one launch (128x128 tile, 4 warps) ----
    {
        dim3 grid(8 + 16, (B_ * T_) / 128);
        gemm_qkv_kernel<<<grid, GEMM_THREADS, GEMM_SMEM_BYTES>>>(
            xh, fh, Wch, Wfh, bc, bf, qh, kvh);
    }
    // ---- 3) flash attention (causal, 128-row blocks, pipelined K/V) ----
    {
        dim3 grid(T_ / 128, H_, B_);
        flash_fp16_kernel<<<grid, 256, FLASH_SMEM_BYTES>>>(qh, kvh, ah);
    }
    // ---- 4) out = attn @ Wp^T + bp -> fp32 ----
    {
        dim3 grid(C_ / 128, (B_ * T_) / 128);
        gemm_out_kernel<<<grid, GEMM_THREADS, GEMM_SMEM_BYTES>>>(ah, Wph, bp, out);
    }
}

// round 16
// speedup vs baseline: 1.5455x; 1.5455x over previous
#include <cuda_runtime.h>
#include <cuda_fp16.h>
#include <cstdint>

// Problem constants
#define B_ 8
#define T_ 1024
#define S_ 1024
#define C_ 1024
#define H_ 16
#define D_ 64

#define NX   ((size_t)B_ * T_ * C_)        // 8M
#define NKV  ((size_t)B_ * S_ * 2 * C_)    // 16M

// fp16 scratch (device globals — no allocation allowed)
__device__ __half g_xh[NX];
__device__ __half g_fh[NX];
__device__ __half g_Wch[(size_t)C_ * C_];
__device__ __half g_Wfh[(size_t)2 * C_ * C_];
__device__ __half g_Wph[(size_t)C_ * C_];
__device__ __half g_qh[NX];
__device__ __half g_kvh[NKV];
__device__ __half g_ah[NX];

__device__ __forceinline__ uint32_t smem_to_u32(const void* p) {
    uint32_t a;
    asm("{ .reg .u64 t; cvta.to.shared.u64 t, %1; cvt.u32.u64 %0, t; }"
        : "=r"(a) : "l"(p));
    return a;
}

#define LDSM_X4(r0, r1, r2, r3, addr) \
    asm volatile("ldmatrix.sync.aligned.m8n8.x4.shared.b16 {%0,%1,%2,%3}, [%4];" \
                 : "=r"(r0), "=r"(r1), "=r"(r2), "=r"(r3) : "r"(addr))

#define LDSM_X4_T(r0, r1, r2, r3, addr) \
    asm volatile("ldmatrix.sync.aligned.m8n8.x4.trans.shared.b16 {%0,%1,%2,%3}, [%4];" \
                 : "=r"(r0), "=r"(r1), "=r"(r2), "=r"(r3) : "r"(addr))

#define MMA_FP16(d, a, b) \
    asm volatile("mma.sync.aligned.m16n8k16.row.col.f32.f16.f16.f32 " \
                 "{%0,%1,%2,%3}, {%4,%5,%6,%7}, {%8,%9}, {%0,%1,%2,%3};" \
                 : "+f"((d)[0]), "+f"((d)[1]), "+f"((d)[2]), "+f"((d)[3]) \
                 : "r"((a)[0]), "r"((a)[1]), "r"((a)[2]), "r"((a)[3]), \
                   "r"((b)[0]), "r"((b)[1]))

#define CP_ASYNC16(dst, src) \
    asm volatile("cp.async.cg.shared.global [%0], [%1], 16;" :: "r"(dst), "l"(src))
#define CP_COMMIT() asm volatile("cp.async.commit_group;")
#define CP_WAIT0()  asm volatile("cp.async.wait_group 0;" ::: "memory")
#define CP_WAIT1()  asm volatile("cp.async.wait_group 1;" ::: "memory")

__device__ __forceinline__ uint32_t pack2h(float a, float b) {
    __half2 t = __floats2half2_rn(a, b);
    return *(uint32_t*)&t;
}

// ===========================================================================
// Fused convert kernel: all 5 tensors in one launch (fp32 * mul -> fp16)
// ===========================================================================
#define CVT_N_X   2097152u
#define CVT_N_W1  262144u
#define CVT_N_W2  524288u
#define CVT_B0    (CVT_N_X)
#define CVT_B1    (2u * CVT_N_X)
#define CVT_B2    (CVT_B1 + CVT_N_W1)
#define CVT_B3    (CVT_B2 + CVT_N_W2)
#define CVT_TOTAL (CVT_B3 + CVT_N_W1)            // 5242880 float4s
#define CVT_BLOCKS (CVT_TOTAL / 256u)            // 20480

__global__ __launch_bounds__(256) void cvt_all_kernel(
    const float* __restrict__ x, const float* __restrict__ f,
    const float* __restrict__ Wc, const float* __restrict__ Wf,
    const float* __restrict__ Wp,
    __half* __restrict__ xh, __half* __restrict__ fh,
    __half* __restrict__ Wch, __half* __restrict__ Wfh,
    __half* __restrict__ Wph)
{
    uint32_t i = blockIdx.x * 256u + threadIdx.x;   // float4 index
    const float* src; __half* dst; float mul = 1.f; uint32_t off;
    if (i < CVT_B0)      { src = x;  dst = xh;  off = i; }
    else if (i < CVT_B1) { src = f;  dst = fh;  off = i - CVT_B0; }
    else if (i < CVT_B2) { src = Wc; dst = Wch; off = i - CVT_B1; mul = 0.125f; }
    else if (i < CVT_B3) { src = Wf; dst = Wfh; off = i - CVT_B2; }
    else                 { src = Wp; dst = Wph; off = i - CVT_B3; }
    float4 v = *(const float4*)(src + (size_t)off * 4);
    __half2 h0 = __floats2half2_rn(v.x * mul, v.y * mul);
    __half2 h1 = __floats2half2_rn(v.z * mul, v.w * mul);
    *(__half2*)(dst + (size_t)off * 4)     = h0;
    *(__half2*)(dst + (size_t)off * 4 + 2) = h1;
}

// ===========================================================================
// fp16 mma.sync GEMM core: C[m,n] = sum_k A[m,k]*B[n,k] + bias[n]*biasmul
// CTA tile 128x128, 4 warps (2x2), warp tile 64x64, BK=64,
// 2-stage cp.async pipeline (single sync/chunk), 3 CTAs/SM (reg-capped 170).
// Inner loop = plain R11 form (ptxas schedules fragments best on its own).
// ===========================================================================
#define RS2 72
#define TILE2_E (128 * RS2)                  // 9216 el / tile
#define STAGE2_E (2 * TILE2_E)               // A + B
#define NSTAGE 2
#define GEMM_SMEM_BYTES (NSTAGE * STAGE2_E * 2)   // 73728 B
#define GEMM_THREADS 128

__device__ __forceinline__ void gemm_load_stage(
    uint32_t sbase, int stage, const __half* __restrict__ srcA,
    const __half* __restrict__ srcB, int K, int k0, int tid)
{
    const uint32_t so = sbase + (uint32_t)(stage * STAGE2_E) * 2;
#pragma unroll
    for (int it = 0; it < 8; it++) {
        int idx = tid + it * GEMM_THREADS;
        int row = idx >> 3;
        int col = (idx & 7) * 8;
        CP_ASYNC16(so + (uint32_t)(row * RS2 + col) * 2,
                   srcA + (size_t)row * K + k0 + col);
    }
#pragma unroll
    for (int it = 0; it < 8; it++) {
        int idx = tid + it * GEMM_THREADS;
        int row = idx >> 3;
        int col = (idx & 7) * 8;
        CP_ASYNC16(so + (uint32_t)(TILE2_E + row * RS2 + col) * 2,
                   srcB + (size_t)row * K + k0 + col);
    }
}

__device__ __forceinline__ void gemm_core(
    uint32_t sbase,
    const __half* __restrict__ srcA,   // A block base (bm applied)
    const __half* __restrict__ srcB,   // B block base (bn applied)
    const float* __restrict__ bias, float biasmul,
    float* __restrict__ Cf, __half* __restrict__ Ch,
    int N, int K, int bm, int bn)
{
    const int tid = threadIdx.x;
    const int lane = tid & 31;
    const int wid = tid >> 5;          // 0..3
    const int wm = (wid & 1) * 64;     // 0,64
    const int wn = (wid >> 1) * 64;    // 0,64

    float acc[4][8][4];
#pragma unroll
    for (int mi = 0; mi < 4; mi++)
#pragma unroll
        for (int nj = 0; nj < 8; nj++)
#pragma unroll
            for (int e = 0; e < 4; e++) acc[mi][nj][e] = 0.f;

    const int a_row_l = lane & 15;
    const int a_col_l = (lane >> 4) * 8;
    const int b_seg = lane >> 3;
    const int b_r8 = lane & 7;
    const int b_row_add = (b_seg >> 1) * 8;
    const int b_col_add = (b_seg & 1) * 8;

    const int nchunk = K >> 6;   // BK=64

    // prologue: stage 0
    gemm_load_stage(sbase, 0, srcA, srcB, K, 0, tid);
    CP_COMMIT();

    for (int ck = 0; ck < nchunk; ck++) {
        CP_WAIT0();          // stage ck&1 fully resident
        __syncthreads();     // all warps done reading stage (ck+1)&1 (from ck-1)

        if (ck + 1 < nchunk) {
            gemm_load_stage(sbase, (ck + 1) & 1, srcA, srcB, K, (ck + 1) << 6, tid);
        }
        CP_COMMIT();

        const uint32_t st = sbase + (uint32_t)((ck & 1) * STAGE2_E) * 2;
        const uint32_t sA = st;
        const uint32_t sB = st + (uint32_t)TILE2_E * 2;

#pragma unroll
        for (int ks = 0; ks < 4; ks++) {
            const int kcol = ks * 16 + a_col_l;
            uint32_t af[4][4];
#pragma unroll
            for (int mi = 0; mi < 4; mi++) {
                uint32_t eo = (uint32_t)((wm + mi * 16 + a_row_l) * RS2 + kcol) * 2;
                LDSM_X4(af[mi][0], af[mi][1], af[mi][2], af[mi][3], sA + eo);
            }
#pragma unroll
            for (int g = 0; g < 4; g++) {
                uint32_t eo = (uint32_t)((wn + g * 16 + b_row_add + b_r8) * RS2 +
                                         ks * 16 + b_col_add) * 2;
                uint32_t bf[4];
                LDSM_X4(bf[0], bf[1], bf[2], bf[3], sB + eo);
#pragma unroll
                for (int half = 0; half < 2; half++) {
                    int nj = g * 2 + half;
                    uint32_t* bp = bf + half * 2;
#pragma unroll
                    for (int mi = 0; mi < 4; mi++)
                        MMA_FP16(acc[mi][nj], af[mi], bp);
                }
            }
        }
    }

    const int er = lane >> 2;
    const int ec = (lane & 3) * 2;
#pragma unroll
    for (int mi = 0; mi < 4; mi++) {
#pragma unroll
        for (int nj = 0; nj < 8; nj++) {
            int m0 = bm + wm + mi * 16 + er;
            int n0 = bn + wn + nj * 8 + ec;
            float b0 = __ldg(bias + n0) * biasmul;
            float b1 = __ldg(bias + n0 + 1) * biasmul;
            float v00 = acc[mi][nj][0] + b0, v01 = acc[mi][nj][1] + b1;
            float v10 = acc[mi][nj][2] + b0, v11 = acc[mi][nj][3] + b1;
            if (Cf) {
                *(float2*)(Cf + (size_t)m0 * N + n0) = make_float2(v00, v01);
                *(float2*)(Cf + (size_t)(m0 + 8) * N + n0) = make_float2(v10, v11);
            } else {
                *(__half2*)(Ch + (size_t)m0 * N + n0) = __floats2half2_rn(v00, v01);
                *(__half2*)(Ch + (size_t)(m0 + 8) * N + n0) = __floats2half2_rn(v10, v11);
            }
        }
    }
}

// merged q + kv projection: blockIdx.x < 8 -> q tile, else kv tile
__global__ __launch_bounds__(GEMM_THREADS, 3) void gemm_qkv_kernel(
    const __half* __restrict__ xh, const __half* __restrict__ fh,
    const __half* __restrict__ Wch, const __half* __restrict__ Wfh,
    const float* __restrict__ bc, const float* __restrict__ bf,
    __half* __restrict__ qh, __half* __restrict__ kvh)
{
    extern __shared__ __half sm[];
    const uint32_t sbase = smem_to_u32(sm);
    const int bm = blockIdx.y * 128;
    if (blockIdx.x < 8) {
        const int bn = blockIdx.x * 128;
        gemm_core(sbase, xh + (size_t)bm * C_, Wch + (size_t)bn * C_,
                  bc, 0.125f, nullptr, qh, C_, C_, bm, bn);
    } else {
        const int bn = (blockIdx.x - 8) * 128;
        gemm_core(sbase, fh + (size_t)bm * C_, Wfh + (size_t)bn * C_,
                  bf, 1.f, nullptr, kvh, 2 * C_, C_, bm, bn);
    }
}

// out-projection: fp32 output
__global__ __launch_bounds__(GEMM_THREADS, 3) void gemm_out_kernel(
    const __half* __restrict__ ah, const __half* __restrict__ Wph,
    const float* __restrict__ bp, float* __restrict__ out)
{
    extern __shared__ __half sm[];
    const uint32_t sbase = smem_to_u32(sm);
    const int bm = blockIdx.y * 128;
    const int bn = blockIdx.x * 128;
    gemm_core(sbase, ah + (size_t)bm * C_, Wph + (size_t)bn * C_,
              bp, 1.f, out, nullptr, C_, C_, bm, bn);
}

// ===========================================================================
// fp16 tensor-core flash attention, causal, d=64, Q pre-scaled by 1/sqrt(d).
// Block = 128 q-rows (8 warps x m16), 64-col K/V tiles, 2-stage cp.async.
// (unchanged — known good)
// ===========================================================================
#define FS2 72
#define FKV2_E (64 * FS2)             // 4608 el per array
#define FSTAGE2_E (2 * FKV2_E)        // K, V
#define FLASH_SMEM_BYTES (2 * FSTAGE2_E * 2)   // 36864 B

__device__ __forceinline__ void flash_ldkv(
    uint32_t sb, uint32_t stoff_bytes, const __half* __restrict__ kvh,
    size_t kvrow, int tid)
{
#pragma unroll
    for (int a = 0; a < 2; a++) {            // 0 = K, 1 = V
        const size_t add = a ? (size_t)C_ : 0;
#pragma unroll
        for (int hf = 0; hf < 2; hf++) {
            int c = tid + hf * 256;          // 0..511
            int row = c >> 3;
            int col = (c & 7) * 8;
            const __half* src = kvh + kvrow + (size_t)row * (2 * C_) + add + col;
            uint32_t dst = sb + stoff_bytes +
                (uint32_t)(a * FKV2_E + row * FS2 + col) * 2;
            CP_ASYNC16(dst, src);
        }
    }
}

__global__ __launch_bounds__(256) void flash_fp16_kernel(
    const __half* __restrict__ qh, const __half* __restrict__ kvh,
    __half* __restrict__ oh)
{
    extern __shared__ __half fsm[];
    const uint32_t sb = smem_to_u32(fsm);

    const int qt = blockIdx.x;            // 0..7  (128-row tiles)
    const int h  = blockIdx.y;
    const int b  = blockIdx.z;
    const int tid = threadIdx.x;
    const int lane = tid & 31;
    const int wid = tid >> 5;
    const int wm = wid * 16;

    const int fr = lane >> 2;
    const int fc = (lane & 3) * 2;

    uint32_t qf[4][4];
    {
        const size_t qrow0 = (size_t)(b * T_ + qt * 128 + wm + fr) * C_ + h * D_;
        const size_t qrow8 = qrow0 + (size_t)8 * C_;
#pragma unroll
        for (int ks = 0; ks < 4; ks++) {
            int c0 = ks * 16 + fc;
            qf[ks][0] = *(const uint32_t*)(qh + qrow0 + c0);
            qf[ks][1] = *(const uint32_t*)(qh + qrow8 + c0);
            qf[ks][2] = *(const uint32_t*)(qh + qrow0 + c0 + 8);
            qf[ks][3] = *(const uint32_t*)(qh + qrow8 + c0 + 8);
        }
    }

    float mrow0 = -1e30f, mrow1 = -1e30f, lrow0 = 0.f, lrow1 = 0.f;
    float oacc[8][4];
#pragma unroll
    for (int j = 0; j < 8; j++)
#pragma unroll
        for (int e = 0; e < 4; e++) oacc[j][e] = 0.f;

    const int b_seg = lane >> 3;
    const int b_r8 = lane & 7;
    const int b_row_add = (b_seg >> 1) * 8;
    const int b_col_add = (b_seg & 1) * 8;
    const int v_row_l = lane & 15;
    const int v_col_l = (lane >> 4) * 8;

    const int row_g0 = qt * 128 + wm + fr;
    const int row_g1 = row_g0 + 8;
    const int st_max = 2 * qt + 1;

    flash_ldkv(sb, 0, kvh, (size_t)(b * S_) * (2 * C_) + h * D_, tid);
    CP_COMMIT();

    for (int st = 0; st <= st_max; st++) {
        __syncthreads();
        if (st + 1 <= st_max) {
            flash_ldkv(sb, (uint32_t)(((st + 1) & 1) * FSTAGE2_E) * 2, kvh,
                       (size_t)(b * S_ + (st + 1) * 64) * (2 * C_) + h * D_, tid);
        }
        CP_COMMIT();
        CP_WAIT1();
        __syncthreads();

        const uint32_t stb = sb + (uint32_t)((st & 1) * FSTAGE2_E) * 2;
        const uint32_t sk_b = stb;
        const uint32_t sv_b = stb + (uint32_t)FKV2_E * 2;

        const bool active = (qt * 128 + wm + 15) >= st * 64;
        if (!active) continue;

        float sacc[8][4];
#pragma unroll
        for (int j = 0; j < 8; j++)
#pragma unroll
            for (int e = 0; e < 4; e++) sacc[j][e] = 0.f;

#pragma unroll
        for (int ks = 0; ks < 4; ks++) {
#pragma unroll
            for (int g = 0; g < 4; g++) {
                uint32_t eo = (uint32_t)((g * 16 + b_row_add + b_r8) * FS2 +
                                         ks * 16 + b_col_add) * 2;
                uint32_t bf[4];
                LDSM_X4(bf[0], bf[1], bf[2], bf[3], sk_b + eo);
#pragma unroll
                for (int half = 0; half < 2; half++) {
                    int nj = g * 2 + half;
                    MMA_FP16(sacc[nj], qf[ks], (bf + half * 2));
                }
            }
        }

        if (st >= 2 * qt) {
#pragma unroll
            for (int nj = 0; nj < 8; nj++) {
#pragma unroll
                for (int e = 0; e < 4; e++) {
                    int col = st * 64 + nj * 8 + fc + (e & 1);
                    int row = (e < 2) ? row_g0 : row_g1;
                    if (col > row) sacc[nj][e] = -1e30f;
                }
            }
        }

        float mx0 = -1e30f, mx1 = -1e30f;
#pragma unroll
        for (int nj = 0; nj < 8; nj++) {
            mx0 = fmaxf(mx0, fmaxf(sacc[nj][0], sacc[nj][1]));
            mx1 = fmaxf(mx1, fmaxf(sacc[nj][2], sacc[nj][3]));
        }
        mx0 = fmaxf(mx0, __shfl_xor_sync(0xffffffffu, mx0, 1));
        mx0 = fmaxf(mx0, __shfl_xor_sync(0xffffffffu, mx0, 2));
        mx1 = fmaxf(mx1, __shfl_xor_sync(0xffffffffu, mx1, 1));
        mx1 = fmaxf(mx1, __shfl_xor_sync(0xffffffffu, mx1, 2));

        float mn0 = fmaxf(mrow0, mx0);
        float mn1 = fmaxf(mrow1, mx1);
        float c0 = __expf(mrow0 - mn0);
        float c1 = __expf(mrow1 - mn1);
        mrow0 = mn0; mrow1 = mn1;

        float rs0 = 0.f, rs1 = 0.f;
        uint32_t pf[4][4];
#pragma unroll
        for (int kp = 0; kp < 4; kp++) {
#pragma unroll
            for (int s2 = 0; s2 < 2; s2++) {
                int nj = kp * 2 + s2;
                float p0 = __expf(sacc[nj][0] - mn0);
                float p1 = __expf(sacc[nj][1] - mn0);
                float p2 = __expf(sacc[nj][2] - mn1);
                float p3 = __expf(sacc[nj][3] - mn1);
                rs0 += p0 + p1;
                rs1 += p2 + p3;
                pf[kp][0 + s2 * 2] = pack2h(p0, p1);
                pf[kp][1 + s2 * 2] = pack2h(p2, p3);
            }
        }
        rs0 += __shfl_xor_sync(0xffffffffu, rs0, 1);
        rs0 += __shfl_xor_sync(0xffffffffu, rs0, 2);
        rs1 += __shfl_xor_sync(0xffffffffu, rs1, 1);
        rs1 += __shfl_xor_sync(0xffffffffu, rs1, 2);
        lrow0 = lrow0 * c0 + rs0;
        lrow1 = lrow1 * c1 + rs1;

#pragma unroll
        for (int j = 0; j < 8; j++) {
            oacc[j][0] *= c0; oacc[j][1] *= c0;
            oacc[j][2] *= c1; oacc[j][3] *= c1;
        }

#pragma unroll
        for (int kp = 0; kp < 4; kp++) {
#pragma unroll
            for (int g = 0; g < 4; g++) {
                uint32_t eo = (uint32_t)((kp * 16 + v_row_l) * FS2 +
                                         g * 16 + v_col_l) * 2;
                uint32_t vf[4];
                LDSM_X4_T(vf[0], vf[1], vf[2], vf[3], sv_b + eo);
#pragma unroll
                for (int half = 0; half < 2; half++) {
                    int njd = g * 2 + half;
                    MMA_FP16(oacc[njd], pf[kp], (vf + half * 2));
                }
            }
        }
    }

    const float inv0 = 1.f / lrow0;
    const float inv1 = 1.f / lrow1;
    const size_t orow0 = (size_t)(b * T_ + row_g0) * C_ + h * D_;
    const size_t orow8 = orow0 + (size_t)8 * C_;
#pragma unroll
    for (int njd = 0; njd < 8; njd++) {
        int col = njd * 8 + fc;
        *(__half2*)(oh + orow0 + col) =
            __floats2half2_rn(oacc[njd][0] * inv0, oacc[njd][1] * inv0);
        *(__half2*)(oh + orow8 + col) =
            __floats2half2_rn(oacc[njd][2] * inv1, oacc[njd][3] * inv1);
    }
}

// ---------------------------------------------------------------------------
// Launch
// ---------------------------------------------------------------------------
extern "C" void kernel_launch(void* const* d_in, const int* in_sizes, int n_in,
                              void* d_out, int out_size)
{
    const float* x       = (const float*)d_in[0];
    const float* feature = (const float*)d_in[1];
    const float* Wc      = (const float*)d_in[2];
    const float* bc      = (const float*)d_in[3];
    const float* Wf      = (const float*)d_in[4];
    const float* bf      = (const float*)d_in[5];
    const float* Wp      = (const float*)d_in[6];
    const float* bp      = (const float*)d_in[7];
    float* out           = (float*)d_out;

    __half *xh, *fh, *Wch, *Wfh, *Wph, *qh, *kvh, *ah;
    cudaGetSymbolAddress((void**)&xh, g_xh);
    cudaGetSymbolAddress((void**)&fh, g_fh);
    cudaGetSymbolAddress((void**)&Wch, g_Wch);
    cudaGetSymbolAddress((void**)&Wfh, g_Wfh);
    cudaGetSymbolAddress((void**)&Wph, g_Wph);
    cudaGetSymbolAddress((void**)&qh, g_qh);
    cudaGetSymbolAddress((void**)&kvh, g_kvh);
    cudaGetSymbolAddress((void**)&ah, g_ah);

    cudaFuncSetAttribute(gemm_qkv_kernel,
                         cudaFuncAttributeMaxDynamicSharedMemorySize, GEMM_SMEM_BYTES);
    cudaFuncSetAttribute(gemm_out_kernel,
                         cudaFuncAttributeMaxDynamicSharedMemorySize, GEMM_SMEM_BYTES);
    cudaFuncSetAttribute(flash_fp16_kernel,
                         cudaFuncAttributeMaxDynamicSharedMemorySize, FLASH_SMEM_BYTES);

    // ---- 0) fused convert: all fp32 inputs -> fp16 (Wc pre-scaled) ----
    cvt_all_kernel<<<CVT_BLOCKS, 256>>>(x, feature, Wc, Wf, Wp,
                                        xh, fh, Wch, Wfh, Wph);

    // ---- 1+2) q and kv projections, one launch (128x128 tile, 4 warps) ----
    {
        dim3 grid(8 + 16, (B_ * T_) / 128);
        gemm_qkv_kernel<<<grid, GEMM_THREADS, GEMM_SMEM_BYTES>>>(
            xh, fh, Wch, Wfh, bc, bf, qh, kvh);
    }
    // ---- 3) flash attention (causal, 128-row blocks, pipelined K/V) ----
    {
        dim3 grid(T_ / 128, H_, B_);
        flash_fp16_kernel<<<grid, 256, FLASH_SMEM_BYTES>>>(qh, kvh, ah);
    }
    // ---- 4) out = attn @ Wp^T + bp -> fp32 ----
    {
        dim3 grid(C_ / 128, (B_ * T_) / 128);
        gemm_out_kernel<<<grid, GEMM_THREADS, GEMM_SMEM_BYTES>>>(ah, Wph, bp, out);
    }
}

// round 17
// speedup vs baseline: 1.6001x; 1.0354x over previous
#include <cuda_runtime.h>
#include <cuda_fp16.h>
#include <cstdint>

// Problem constants
#define B_ 8
#define T_ 1024
#define S_ 1024
#define C_ 1024
#define H_ 16
#define D_ 64

#define NX   ((size_t)B_ * T_ * C_)        // 8M
#define NKV  ((size_t)B_ * S_ * 2 * C_)    // 16M

// fp16 scratch (device globals — no allocation allowed)
__device__ __half g_xh[NX];
__device__ __half g_fh[NX];
__device__ __half g_Wch[(size_t)C_ * C_];
__device__ __half g_Wfh[(size_t)2 * C_ * C_];
__device__ __half g_Wph[(size_t)C_ * C_];
__device__ __half g_qh[NX];
__device__ __half g_kvh[NKV];
__device__ __half g_ah[NX];

__device__ __forceinline__ uint32_t smem_to_u32(const void* p) {
    uint32_t a;
    asm("{ .reg .u64 t; cvta.to.shared.u64 t, %1; cvt.u32.u64 %0, t; }"
        : "=r"(a) : "l"(p));
    return a;
}

#define LDSM_X4(r0, r1, r2, r3, addr) \
    asm volatile("ldmatrix.sync.aligned.m8n8.x4.shared.b16 {%0,%1,%2,%3}, [%4];" \
                 : "=r"(r0), "=r"(r1), "=r"(r2), "=r"(r3) : "r"(addr))

#define LDSM_X4_T(r0, r1, r2, r3, addr) \
    asm volatile("ldmatrix.sync.aligned.m8n8.x4.trans.shared.b16 {%0,%1,%2,%3}, [%4];" \
                 : "=r"(r0), "=r"(r1), "=r"(r2), "=r"(r3) : "r"(addr))

#define MMA_FP16(d, a, b) \
    asm volatile("mma.sync.aligned.m16n8k16.row.col.f32.f16.f16.f32 " \
                 "{%0,%1,%2,%3}, {%4,%5,%6,%7}, {%8,%9}, {%0,%1,%2,%3};" \
                 : "+f"((d)[0]), "+f"((d)[1]), "+f"((d)[2]), "+f"((d)[3]) \
                 : "r"((a)[0]), "r"((a)[1]), "r"((a)[2]), "r"((a)[3]), \
                   "r"((b)[0]), "r"((b)[1]))

#define CP_ASYNC16(dst, src) \
    asm volatile("cp.async.cg.shared.global [%0], [%1], 16;" :: "r"(dst), "l"(src))
#define CP_COMMIT() asm volatile("cp.async.commit_group;")
#define CP_WAIT0()  asm volatile("cp.async.wait_group 0;" ::: "memory")
#define CP_WAIT1()  asm volatile("cp.async.wait_group 1;" ::: "memory")

__device__ __forceinline__ uint32_t pack2h(float a, float b) {
    __half2 t = __floats2half2_rn(a, b);
    return *(uint32_t*)&t;
}

// ===========================================================================
// Fused convert kernel: all 5 tensors in one launch (fp32 * mul -> fp16)
// ===========================================================================
#define CVT_N_X   2097152u
#define CVT_N_W1  262144u
#define CVT_N_W2  524288u
#define CVT_B0    (CVT_N_X)
#define CVT_B1    (2u * CVT_N_X)
#define CVT_B2    (CVT_B1 + CVT_N_W1)
#define CVT_B3    (CVT_B2 + CVT_N_W2)
#define CVT_TOTAL (CVT_B3 + CVT_N_W1)            // 5242880 float4s
#define CVT_BLOCKS (CVT_TOTAL / 256u)            // 20480

__global__ __launch_bounds__(256) void cvt_all_kernel(
    const float* __restrict__ x, const float* __restrict__ f,
    const float* __restrict__ Wc, const float* __restrict__ Wf,
    const float* __restrict__ Wp,
    __half* __restrict__ xh, __half* __restrict__ fh,
    __half* __restrict__ Wch, __half* __restrict__ Wfh,
    __half* __restrict__ Wph)
{
    uint32_t i = blockIdx.x * 256u + threadIdx.x;   // float4 index
    const float* src; __half* dst; float mul = 1.f; uint32_t off;
    if (i < CVT_B0)      { src = x;  dst = xh;  off = i; }
    else if (i < CVT_B1) { src = f;  dst = fh;  off = i - CVT_B0; }
    else if (i < CVT_B2) { src = Wc; dst = Wch; off = i - CVT_B1; mul = 0.125f; }
    else if (i < CVT_B3) { src = Wf; dst = Wfh; off = i - CVT_B2; }
    else                 { src = Wp; dst = Wph; off = i - CVT_B3; }
    float4 v = *(const float4*)(src + (size_t)off * 4);
    __half2 h0 = __floats2half2_rn(v.x * mul, v.y * mul);
    __half2 h1 = __floats2half2_rn(v.z * mul, v.w * mul);
    *(__half2*)(dst + (size_t)off * 4)     = h0;
    *(__half2*)(dst + (size_t)off * 4 + 2) = h1;
}

// ===========================================================================
// fp16 mma.sync GEMM core: C[m,n] = sum_k A[m,k]*B[n,k] + bias[n]*biasmul
// CTA tile 128x128, 4 warps (2x2), warp tile 64x64, BK=64,
// 2-stage cp.async pipeline (single sync/chunk), 3 CTAs/SM.
// PERSISTENT: callers loop this core over tiles (no wave-quantization tail).
// ===========================================================================
#define RS2 72
#define TILE2_E (128 * RS2)                  // 9216 el / tile
#define STAGE2_E (2 * TILE2_E)               // A + B
#define NSTAGE 2
#define GEMM_SMEM_BYTES (NSTAGE * STAGE2_E * 2)   // 73728 B
#define GEMM_THREADS 128
#define NUM_SMS 152
#define GEMM_GRID (NUM_SMS * 3)              // 456 persistent CTAs

__device__ __forceinline__ void gemm_load_stage(
    uint32_t sbase, int stage, const __half* __restrict__ srcA,
    const __half* __restrict__ srcB, int K, int k0, int tid)
{
    const uint32_t so = sbase + (uint32_t)(stage * STAGE2_E) * 2;
#pragma unroll
    for (int it = 0; it < 8; it++) {
        int idx = tid + it * GEMM_THREADS;
        int row = idx >> 3;
        int col = (idx & 7) * 8;
        CP_ASYNC16(so + (uint32_t)(row * RS2 + col) * 2,
                   srcA + (size_t)row * K + k0 + col);
    }
#pragma unroll
    for (int it = 0; it < 8; it++) {
        int idx = tid + it * GEMM_THREADS;
        int row = idx >> 3;
        int col = (idx & 7) * 8;
        CP_ASYNC16(so + (uint32_t)(TILE2_E + row * RS2 + col) * 2,
                   srcB + (size_t)row * K + k0 + col);
    }
}

__device__ __forceinline__ void gemm_core(
    uint32_t sbase,
    const __half* __restrict__ srcA,   // A block base (bm applied)
    const __half* __restrict__ srcB,   // B block base (bn applied)
    const float* __restrict__ bias, float biasmul,
    float* __restrict__ Cf, __half* __restrict__ Ch,
    int N, int K, int bm, int bn)
{
    const int tid = threadIdx.x;
    const int lane = tid & 31;
    const int wid = tid >> 5;          // 0..3
    const int wm = (wid & 1) * 64;     // 0,64
    const int wn = (wid >> 1) * 64;    // 0,64

    float acc[4][8][4];
#pragma unroll
    for (int mi = 0; mi < 4; mi++)
#pragma unroll
        for (int nj = 0; nj < 8; nj++)
#pragma unroll
            for (int e = 0; e < 4; e++) acc[mi][nj][e] = 0.f;

    const int a_row_l = lane & 15;
    const int a_col_l = (lane >> 4) * 8;
    const int b_seg = lane >> 3;
    const int b_r8 = lane & 7;
    const int b_row_add = (b_seg >> 1) * 8;
    const int b_col_add = (b_seg & 1) * 8;

    const int nchunk = K >> 6;   // BK=64

    // prologue: stage 0
    gemm_load_stage(sbase, 0, srcA, srcB, K, 0, tid);
    CP_COMMIT();

    for (int ck = 0; ck < nchunk; ck++) {
        CP_WAIT0();          // stage ck&1 fully resident
        __syncthreads();     // all warps done reading stage (ck+1)&1 (from ck-1)

        if (ck + 1 < nchunk) {
            gemm_load_stage(sbase, (ck + 1) & 1, srcA, srcB, K, (ck + 1) << 6, tid);
        }
        CP_COMMIT();

        const uint32_t st = sbase + (uint32_t)((ck & 1) * STAGE2_E) * 2;
        const uint32_t sA = st;
        const uint32_t sB = st + (uint32_t)TILE2_E * 2;

#pragma unroll
        for (int ks = 0; ks < 4; ks++) {
            const int kcol = ks * 16 + a_col_l;
            uint32_t af[4][4];
#pragma unroll
            for (int mi = 0; mi < 4; mi++) {
                uint32_t eo = (uint32_t)((wm + mi * 16 + a_row_l) * RS2 + kcol) * 2;
                LDSM_X4(af[mi][0], af[mi][1], af[mi][2], af[mi][3], sA + eo);
            }
#pragma unroll
            for (int g = 0; g < 4; g++) {
                uint32_t eo = (uint32_t)((wn + g * 16 + b_row_add + b_r8) * RS2 +
                                         ks * 16 + b_col_add) * 2;
                uint32_t bf[4];
                LDSM_X4(bf[0], bf[1], bf[2], bf[3], sB + eo);
#pragma unroll
                for (int half = 0; half < 2; half++) {
                    int nj = g * 2 + half;
                    uint32_t* bp = bf + half * 2;
#pragma unroll
                    for (int mi = 0; mi < 4; mi++)
                        MMA_FP16(acc[mi][nj], af[mi], bp);
                }
            }
        }
    }

    const int er = lane >> 2;
    const int ec = (lane & 3) * 2;
#pragma unroll
    for (int mi = 0; mi < 4; mi++) {
#pragma unroll
        for (int nj = 0; nj < 8; nj++) {
            int m0 = bm + wm + mi * 16 + er;
            int n0 = bn + wn + nj * 8 + ec;
            float b0 = __ldg(bias + n0) * biasmul;
            float b1 = __ldg(bias + n0 + 1) * biasmul;
            float v00 = acc[mi][nj][0] + b0, v01 = acc[mi][nj][1] + b1;
            float v10 = acc[mi][nj][2] + b0, v11 = acc[mi][nj][3] + b1;
            if (Cf) {
                *(float2*)(Cf + (size_t)m0 * N + n0) = make_float2(v00, v01);
                *(float2*)(Cf + (size_t)(m0 + 8) * N + n0) = make_float2(v10, v11);
            } else {
                *(__half2*)(Ch + (size_t)m0 * N + n0) = __floats2half2_rn(v00, v01);
                *(__half2*)(Ch + (size_t)(m0 + 8) * N + n0) = __floats2half2_rn(v10, v11);
            }
        }
    }
}

// persistent merged q + kv projection: tiles 0..1535
//   tile -> bx = tile % 24 (bx<8: q n-tile; else kv n-tile), by = tile / 24
#define QKV_TILES (24 * 64)
__global__ __launch_bounds__(GEMM_THREADS, 3) void gemm_qkv_kernel(
    const __half* __restrict__ xh, const __half* __restrict__ fh,
    const __half* __restrict__ Wch, const __half* __restrict__ Wfh,
    const float* __restrict__ bc, const float* __restrict__ bf,
    __half* __restrict__ qh, __half* __restrict__ kvh)
{
    extern __shared__ __half sm[];
    const uint32_t sbase = smem_to_u32(sm);
    for (int tile = blockIdx.x; tile < QKV_TILES; tile += GEMM_GRID) {
        const int bx = tile % 24;
        const int bm = (tile / 24) * 128;
        if (bx < 8) {
            const int bn = bx * 128;
            gemm_core(sbase, xh + (size_t)bm * C_, Wch + (size_t)bn * C_,
                      bc, 0.125f, nullptr, qh, C_, C_, bm, bn);
        } else {
            const int bn = (bx - 8) * 128;
            gemm_core(sbase, fh + (size_t)bm * C_, Wfh + (size_t)bn * C_,
                      bf, 1.f, nullptr, kvh, 2 * C_, C_, bm, bn);
        }
        __syncthreads();   // smem reuse fence between tiles
    }
}

// persistent out-projection: tiles 0..511, tile -> bx = tile % 8, by = tile / 8
#define OUT_TILES (8 * 64)
__global__ __launch_bounds__(GEMM_THREADS, 3) void gemm_out_kernel(
    const __half* __restrict__ ah, const __half* __restrict__ Wph,
    const float* __restrict__ bp, float* __restrict__ out)
{
    extern __shared__ __half sm[];
    const uint32_t sbase = smem_to_u32(sm);
    for (int tile = blockIdx.x; tile < OUT_TILES; tile += GEMM_GRID) {
        const int bn = (tile % 8) * 128;
        const int bm = (tile / 8) * 128;
        gemm_core(sbase, ah + (size_t)bm * C_, Wph + (size_t)bn * C_,
                  bp, 1.f, out, nullptr, C_, C_, bm, bn);
        __syncthreads();   // smem reuse fence between tiles
    }
}

// ===========================================================================
// fp16 tensor-core flash attention, causal, d=64, Q pre-scaled by 1/sqrt(d).
// Block = 128 q-rows (8 warps x m16), 64-col K/V tiles, 2-stage cp.async.
// (unchanged — known good)
// ===========================================================================
#define FS2 72
#define FKV2_E (64 * FS2)             // 4608 el per array
#define FSTAGE2_E (2 * FKV2_E)        // K, V
#define FLASH_SMEM_BYTES (2 * FSTAGE2_E * 2)   // 36864 B

__device__ __forceinline__ void flash_ldkv(
    uint32_t sb, uint32_t stoff_bytes, const __half* __restrict__ kvh,
    size_t kvrow, int tid)
{
#pragma unroll
    for (int a = 0; a < 2; a++) {            // 0 = K, 1 = V
        const size_t add = a ? (size_t)C_ : 0;
#pragma unroll
        for (int hf = 0; hf < 2; hf++) {
            int c = tid + hf * 256;          // 0..511
            int row = c >> 3;
            int col = (c & 7) * 8;
            const __half* src = kvh + kvrow + (size_t)row * (2 * C_) + add + col;
            uint32_t dst = sb + stoff_bytes +
                (uint32_t)(a * FKV2_E + row * FS2 + col) * 2;
            CP_ASYNC16(dst, src);
        }
    }
}

__global__ __launch_bounds__(256) void flash_fp16_kernel(
    const __half* __restrict__ qh, const __half* __restrict__ kvh,
    __half* __restrict__ oh)
{
    extern __shared__ __half fsm[];
    const uint32_t sb = smem_to_u32(fsm);

    const int qt = blockIdx.x;            // 0..7  (128-row tiles)
    const int h  = blockIdx.y;
    const int b  = blockIdx.z;
    const int tid = threadIdx.x;
    const int lane = tid & 31;
    const int wid = tid >> 5;
    const int wm = wid * 16;

    const int fr = lane >> 2;
    const int fc = (lane & 3) * 2;

    uint32_t qf[4][4];
    {
        const size_t qrow0 = (size_t)(b * T_ + qt * 128 + wm + fr) * C_ + h * D_;
        const size_t qrow8 = qrow0 + (size_t)8 * C_;
#pragma unroll
        for (int ks = 0; ks < 4; ks++) {
            int c0 = ks * 16 + fc;
            qf[ks][0] = *(const uint32_t*)(qh + qrow0 + c0);
            qf[ks][1] = *(const uint32_t*)(qh + qrow8 + c0);
            qf[ks][2] = *(const uint32_t*)(qh + qrow0 + c0 + 8);
            qf[ks][3] = *(const uint32_t*)(qh + qrow8 + c0 + 8);
        }
    }

    float mrow0 = -1e30f, mrow1 = -1e30f, lrow0 = 0.f, lrow1 = 0.f;
    float oacc[8][4];
#pragma unroll
    for (int j = 0; j < 8; j++)
#pragma unroll
        for (int e = 0; e < 4; e++) oacc[j][e] = 0.f;

    const int b_seg = lane >> 3;
    const int b_r8 = lane & 7;
    const int b_row_add = (b_seg >> 1) * 8;
    const int b_col_add = (b_seg & 1) * 8;
    const int v_row_l = lane & 15;
    const int v_col_l = (lane >> 4) * 8;

    const int row_g0 = qt * 128 + wm + fr;
    const int row_g1 = row_g0 + 8;
    const int st_max = 2 * qt + 1;

    flash_ldkv(sb, 0, kvh, (size_t)(b * S_) * (2 * C_) + h * D_, tid);
    CP_COMMIT();

    for (int st = 0; st <= st_max; st++) {
        __syncthreads();
        if (st + 1 <= st_max) {
            flash_ldkv(sb, (uint32_t)(((st + 1) & 1) * FSTAGE2_E) * 2, kvh,
                       (size_t)(b * S_ + (st + 1) * 64) * (2 * C_) + h * D_, tid);
        }
        CP_COMMIT();
        CP_WAIT1();
        __syncthreads();

        const uint32_t stb = sb + (uint32_t)((st & 1) * FSTAGE2_E) * 2;
        const uint32_t sk_b = stb;
        const uint32_t sv_b = stb + (uint32_t)FKV2_E * 2;

        const bool active = (qt * 128 + wm + 15) >= st * 64;
        if (!active) continue;

        float sacc[8][4];
#pragma unroll
        for (int j = 0; j < 8; j++)
#pragma unroll
            for (int e = 0; e < 4; e++) sacc[j][e] = 0.f;

#pragma unroll
        for (int ks = 0; ks < 4; ks++) {
#pragma unroll
            for (int g = 0; g < 4; g++) {
                uint32_t eo = (uint32_t)((g * 16 + b_row_add + b_r8) * FS2 +
                                         ks * 16 + b_col_add) * 2;
                uint32_t bf[4];
                LDSM_X4(bf[0], bf[1], bf[2], bf[3], sk_b + eo);
#pragma unroll
                for (int half = 0; half < 2; half++) {
                    int nj = g * 2 + half;
                    MMA_FP16(sacc[nj], qf[ks], (bf + half * 2));
                }
            }
        }

        if (st >= 2 * qt) {
#pragma unroll
            for (int nj = 0; nj < 8; nj++) {
#pragma unroll
                for (int e = 0; e < 4; e++) {
                    int col = st * 64 + nj * 8 + fc + (e & 1);
                    int row = (e < 2) ? row_g0 : row_g1;
                    if (col > row) sacc[nj][e] = -1e30f;
                }
            }
        }

        float mx0 = -1e30f, mx1 = -1e30f;
#pragma unroll
        for (int nj = 0; nj < 8; nj++) {
            mx0 = fmaxf(mx0, fmaxf(sacc[nj][0], sacc[nj][1]));
            mx1 = fmaxf(mx1, fmaxf(sacc[nj][2], sacc[nj][3]));
        }
        mx0 = fmaxf(mx0, __shfl_xor_sync(0xffffffffu, mx0, 1));
        mx0 = fmaxf(mx0, __shfl_xor_sync(0xffffffffu, mx0, 2));
        mx1 = fmaxf(mx1, __shfl_xor_sync(0xffffffffu, mx1, 1));
        mx1 = fmaxf(mx1, __shfl_xor_sync(0xffffffffu, mx1, 2));

        float mn0 = fmaxf(mrow0, mx0);
        float mn1 = fmaxf(mrow1, mx1);
        float c0 = __expf(mrow0 - mn0);
        float c1 = __expf(mrow1 - mn1);
        mrow0 = mn0; mrow1 = mn1;

        float rs0 = 0.f, rs1 = 0.f;
        uint32_t pf[4][4];
#pragma unroll
        for (int kp = 0; kp < 4; kp++) {
#pragma unroll
            for (int s2 = 0; s2 < 2; s2++) {
                int nj = kp * 2 + s2;
                float p0 = __expf(sacc[nj][0] - mn0);
                float p1 = __expf(sacc[nj][1] - mn0);
                float p2 = __expf(sacc[nj][2] - mn1);
                float p3 = __expf(sacc[nj][3] - mn1);
                rs0 += p0 + p1;
                rs1 += p2 + p3;
                pf[kp][0 + s2 * 2] = pack2h(p0, p1);
                pf[kp][1 + s2 * 2] = pack2h(p2, p3);
            }
        }
        rs0 += __shfl_xor_sync(0xffffffffu, rs0, 1);
        rs0 += __shfl_xor_sync(0xffffffffu, rs0, 2);
        rs1 += __shfl_xor_sync(0xffffffffu, rs1, 1);
        rs1 += __shfl_xor_sync(0xffffffffu, rs1, 2);
        lrow0 = lrow0 * c0 + rs0;
        lrow1 = lrow1 * c1 + rs1;

#pragma unroll
        for (int j = 0; j < 8; j++) {
            oacc[j][0] *= c0; oacc[j][1] *= c0;
            oacc[j][2] *= c1; oacc[j][3] *= c1;
        }

#pragma unroll
        for (int kp = 0; kp < 4; kp++) {
#pragma unroll
            for (int g = 0; g < 4; g++) {
                uint32_t eo = (uint32_t)((kp * 16 + v_row_l) * FS2 +
                                         g * 16 + v_col_l) * 2;
                uint32_t vf[4];
                LDSM_X4_T(vf[0], vf[1], vf[2], vf[3], sv_b + eo);
#pragma unroll
                for (int half = 0; half < 2; half++) {
                    int njd = g * 2 + half;
                    MMA_FP16(oacc[njd], pf[kp], (vf + half * 2));
                }
            }
        }
    }

    const float inv0 = 1.f / lrow0;
    const float inv1 = 1.f / lrow1;
    const size_t orow0 = (size_t)(b * T_ + row_g0) * C_ + h * D_;
    const size_t orow8 = orow0 + (size_t)8 * C_;
#pragma unroll
    for (int njd = 0; njd < 8; njd++) {
        int col = njd * 8 + fc;
        *(__half2*)(oh + orow0 + col) =
            __floats2half2_rn(oacc[njd][0] * inv0, oacc[njd][1] * inv0);
        *(__half2*)(oh + orow8 + col) =
            __floats2half2_rn(oacc[njd][2] * inv1, oacc[njd][3] * inv1);
    }
}

// ---------------------------------------------------------------------------
// Launch
// ---------------------------------------------------------------------------
extern "C" void kernel_launch(void* const* d_in, const int* in_sizes, int n_in,
                              void* d_out, int out_size)
{
    const float* x       = (const float*)d_in[0];
    const float* feature = (const float*)d_in[1];
    const float* Wc      = (const float*)d_in[2];
    const float* bc      = (const float*)d_in[3];
    const float* Wf      = (const float*)d_in[4];
    const float* bf      = (const float*)d_in[5];
    const float* Wp      = (const float*)d_in[6];
    const float* bp      = (const float*)d_in[7];
    float* out           = (float*)d_out;

    __half *xh, *fh, *Wch, *Wfh, *Wph, *qh, *kvh, *ah;
    cudaGetSymbolAddress((void**)&xh, g_xh);
    cudaGetSymbolAddress((void**)&fh, g_fh);
    cudaGetSymbolAddress((void**)&Wch, g_Wch);
    cudaGetSymbolAddress((void**)&Wfh, g_Wfh);
    cudaGetSymbolAddress((void**)&Wph, g_Wph);
    cudaGetSymbolAddress((void**)&qh, g_qh);
    cudaGetSymbolAddress((void**)&kvh, g_kvh);
    cudaGetSymbolAddress((void**)&ah, g_ah);

    cudaFuncSetAttribute(gemm_qkv_kernel,
                         cudaFuncAttributeMaxDynamicSharedMemorySize, GEMM_SMEM_BYTES);
    cudaFuncSetAttribute(gemm_out_kernel,
                         cudaFuncAttributeMaxDynamicSharedMemorySize, GEMM_SMEM_BYTES);
    cudaFuncSetAttribute(flash_fp16_kernel,
                         cudaFuncAttributeMaxDynamicSharedMemorySize, FLASH_SMEM_BYTES);

    // ---- 0) fused convert: all fp32 inputs -> fp16 (Wc pre-scaled) ----
    cvt_all_kernel<<<CVT_BLOCKS, 256>>>(x, feature, Wc, Wf, Wp,
                                        xh, fh, Wch, Wfh, Wph);

    // ---- 1+2) q and kv projections: persistent 456-CTA launch ----
    gemm_qkv_kernel<<<GEMM_GRID, GEMM_THREADS, GEMM_SMEM_BYTES>>>(
        xh, fh, Wch, Wfh, bc, bf, qh, kvh);

    // ---- 3) flash attention (causal, 128-row blocks, pipelined K/V) ----
    {
        dim3 grid(T_ / 128, H_, B_);
        flash_fp16_kernel<<<grid, 256, FLASH_SMEM_BYTES>>>(qh, kvh, ah);
    }
    // ---- 4) out = attn @ Wp^T + bp -> fp32 (persistent) ----
    gemm_out_kernel<<<GEMM_GRID, GEMM_THREADS, GEMM_SMEM_BYTES>>>(ah, Wph, bp, out);
}